// round 17
// baseline (speedup 1.0000x reference)
#include <cuda_runtime.h>
#include <cuda_fp16.h>
#include <cstdint>

#define SEQ 256
#define B_  32
#define TILE 4096      // 64*64 floats
#define RSLOT 8        // ring slots (8KB f16 each)

// LAYOUT L4 (verified): tile (b,t) at (t*32+b)*TILE; interior transposed:
// element (i,j) at f32 offset j*64 + i.

__device__ float g_fv[32][64];
__device__ float g_bv[32][64];
__device__ float g_fo[32];
__device__ float g_bo[32];
__device__ float g_sc[32];
__device__ int   g_ct[32];
__device__ int   g_done;

__device__ __forceinline__ int bf16_ok(unsigned h) {
    const float g = __uint_as_float(h << 16);
    return (h == 0u) || (g >= 1.f && g < 64.f && g == floorf(g));
}
__device__ __forceinline__ int decode_tgt(const unsigned* tu, int mode, int e) {
    int v;
    if      (mode == 0) v = (int)tu[2 * e];
    else if (mode == 1) v = (int)tu[e];
    else if (mode == 2) v = (int)((tu[e >> 1] >> ((e & 1) * 16)) & 0xFFFFu);
    else if (mode == 3) v = (int)((tu[e >> 2] >> ((e & 3) * 8)) & 0xFFu);
    else if (mode == 4) v = (int)__uint_as_float(tu[e]);
    else if (mode == 5) v = (int)__uint_as_float(((tu[e >> 1] >> ((e & 1) * 16)) & 0xFFFFu) << 16);
    else                v = (int)__hiloint2double(tu[2 * e + 1], tu[2 * e]);
    return v & 63;
}

__device__ __forceinline__ unsigned pack_exp(float a, float b) {
    const float L2E = 1.4426950408889634f;
    __half2 h = h2exp2(__floats2half2_rn(a * L2E, b * L2E));
    return *(unsigned*)&h;
}

// -------------------------------------------------------------------------
// grid = 64, 512 threads. Block blk: batch b = blk>>1, dir = blk&1.
// Warps 0-3 (threads 0-127): chain (4 SMSPs, 16 outputs each).
// Warps 4-15: producers — LDG + exp(f16x2) + swizzled STS into an 8-slot
// ring, loosely synced via ready[]/chain_pos flags. bwd producers transpose.
// P_eff layout: row r (output), 32 f16x2 words; word jw at (jw+2(r&15))&31.
// -------------------------------------------------------------------------
__global__ void __launch_bounds__(512) crf_fused(const float* __restrict__ emits,
                                                 const unsigned char* __restrict__ mask,
                                                 const unsigned* __restrict__ tu,
                                                 float* __restrict__ out)
{
    extern __shared__ unsigned ring[];          // RSLOT * 2048 u32 = 64KB
    __shared__ __align__(16) float Abuf[2][64];
    __shared__ __align__(16) float sMax[4];
    __shared__ unsigned char sM[256];
    __shared__ float sRed2[2];
    __shared__ int ready[RSLOT];
    __shared__ int arrive[RSLOT];
    __shared__ int chain_pos;
    __shared__ float sv[16];
    __shared__ int   scnt[16];
    __shared__ double sAcc[16];
    __shared__ int   sCt2[16];

    const int blk = blockIdx.x;
    const int tid = threadIdx.x;
    const int b = blk >> 1, dir = blk & 1;
    const int wid = tid >> 5, lane = tid & 31;
    const int nsteps = dir ? 128 : 127;

    if (tid < RSLOT) { ready[tid] = -1; arrive[tid] = 0; }
    if (tid == 0) chain_pos = -1;
    if (tid < 256) sM[tid] = mask[b * SEQ + tid];

    // alpha0 (buffer 0)
    float m0 = 0.f;
    if (dir == 0) {
        float e0 = (tid < 64) ? emits[(size_t)b * TILE + tid * 64] : -1e30f;
        if (tid < 64) {
            float v = e0;
            #pragma unroll
            for (int o = 16; o; o >>= 1) v = fmaxf(v, __shfl_xor_sync(~0u, v, o));
            if ((tid & 31) == 0) sRed2[tid >> 5] = v;
        }
        __syncthreads();
        m0 = fmaxf(sRed2[0], sRed2[1]);
        if (tid < 64) Abuf[0][tid] = __expf(e0 - m0);
    } else {
        if (tid < 64) Abuf[0][tid] = 1.f;
    }
    __syncthreads();   // flags + alpha0 + sM visible to everyone

    int K = 0;

    if (wid < 4) {
        // ===================== CHAIN (threads 0-127) =====================
        const int o = 16 * wid + (lane & 15);
        const int h = lane >> 4;
        int offk[8];
        #pragma unroll
        for (int k = 0; k < 8; k++)
            offk[k] = (16 * h + 2 * k + 2 * (o & 15)) & 31;
        const unsigned* rowbase0 = ring + o * 32;

        int cb = 0;
        for (int s = 0; s < nsteps; s++) {
            const int slot = s & (RSLOT - 1);
            {   // wait tile ready (producers usually ahead)
                volatile int* rp = ready + slot;
                while (*rp != s) { }
            }
            const unsigned* rowp = rowbase0 + slot * 2048;
            const float* av = Abuf[cb] + 32 * h;

            float acc0 = 0.f, acc1 = 0.f, acc2 = 0.f, acc3 = 0.f;
            #pragma unroll
            for (int k = 0; k < 8; k++) {
                const uint2 v = *(const uint2*)(rowp + offk[k]);
                const float4 a = *(const float4*)(av + 4 * k);
                const float2 f0 = __half22float2(*(const __half2*)&v.x);
                const float2 f1 = __half22float2(*(const __half2*)&v.y);
                if ((k & 3) == 0) { acc0 += f0.x * a.x + f0.y * a.y; acc0 += f1.x * a.z + f1.y * a.w; }
                else if ((k & 3) == 1) { acc1 += f0.x * a.x + f0.y * a.y; acc1 += f1.x * a.z + f1.y * a.w; }
                else if ((k & 3) == 2) { acc2 += f0.x * a.x + f0.y * a.y; acc2 += f1.x * a.z + f1.y * a.w; }
                else { acc3 += f0.x * a.x + f0.y * a.y; acc3 += f1.x * a.z + f1.y * a.w; }
            }
            float y = (acc0 + acc1) + (acc2 + acc3);
            y += __shfl_xor_sync(~0u, y, 16);     // combine halves

            const int t = dir ? 255 - s : 1 + s;
            const bool msk = sM[t] != 0;

            if ((s & 7) == 7) {                   // renorm (uniform branch)
                float m = y;
                m = fmaxf(m, __shfl_xor_sync(~0u, m, 1));
                m = fmaxf(m, __shfl_xor_sync(~0u, m, 2));
                m = fmaxf(m, __shfl_xor_sync(~0u, m, 4));
                m = fmaxf(m, __shfl_xor_sync(~0u, m, 8));
                if (lane == 0) sMax[wid] = m;
                asm volatile("bar.sync 1, 128;" ::: "memory");
                const float4 x = *(const float4*)&sMax[0];
                const float gm = fmaxf(fmaxf(x.x, x.y), fmaxf(x.z, x.w));
                if (msk) {
                    const int kx = ((__float_as_int(gm) >> 23) & 0xFF) - 127;  // ilogb
                    y *= __int_as_float((127 - kx) << 23);                     // exact 2^-kx
                    K += kx;
                }
            }

            if (lane < 16) Abuf[cb ^ 1][o] = msk ? y : Abuf[cb][o];
            asm volatile("bar.sync 1, 128;" ::: "memory");
            if (tid == 0) *(volatile int*)&chain_pos = s;
            cb ^= 1;
        }
    } else {
        // ===================== PRODUCERS (warps 4-15) ====================
        const int g  = wid - 4;
        const int gq = g & 3;        // quarter of the tile
        const int gt = g >> 2;       // step group: handles s ≡ gt (mod 3)
        float4 L[8], N[8];

        auto load_assign = [&](int s, float4 (&R)[8]) {
            const int t = dir ? 255 - s : 1 + s;
            const float* tp = emits + (size_t)(t * B_ + b) * TILE;
            if (dir == 0) {
                const int r = 16 * gq + (lane >> 1);
                const int hh = lane & 1;
                const float* src = tp + r * 64 + 32 * hh;
                #pragma unroll
                for (int k = 0; k < 8; k++) R[k] = *(const float4*)(src + 4 * k);
            } else {
                const int c = lane & 15, ph = lane >> 4;
                const float* src = tp + 4 * c;
                #pragma unroll
                for (int m = 0; m < 4; m++) {
                    const int jA = 16 * gq + 8 * ph + 2 * m;
                    R[2 * m]     = *(const float4*)(src + jA * 64);
                    R[2 * m + 1] = *(const float4*)(src + (jA + 1) * 64);
                }
            }
        };

        if (gt < nsteps) load_assign(gt, L);

        for (int s = gt; s < nsteps; s += 3) {
            if (s + 3 < nsteps) load_assign(s + 3, N);

            // wait: slot occupant (s-RSLOT) consumed
            {
                volatile int* cp = &chain_pos;
                while (*cp < s - RSLOT) __nanosleep(40);
            }
            const int slot = s & (RSLOT - 1);
            unsigned* slotp = ring + slot * 2048;

            if (dir == 0) {
                const int r = 16 * gq + (lane >> 1);
                const int hh = lane & 1;
                #pragma unroll
                for (int k = 0; k < 8; k++) {
                    uint2 val;
                    val.x = pack_exp(L[k].x, L[k].y);
                    val.y = pack_exp(L[k].z, L[k].w);
                    const int phys = (16 * hh + 2 * k + 2 * (r & 15)) & 31;
                    *(uint2*)(slotp + r * 32 + phys) = val;
                }
            } else {
                const int c = lane & 15, ph = lane >> 4;
                #pragma unroll
                for (int m = 0; m < 4; m++) {
                    const int jw = 8 * gq + 4 * ph + m;
                    const float* fa = (const float*)&L[2 * m];
                    const float* fb = (const float*)&L[2 * m + 1];
                    #pragma unroll
                    for (int q = 0; q < 4; q++) {
                        const int i = 4 * c + q;
                        slotp[i * 32 + ((jw + 2 * (i & 15)) & 31)] = pack_exp(fa[q], fb[q]);
                    }
                }
            }

            __threadfence_block();
            if (lane == 0) {
                const int old = atomicAdd(&arrive[slot], 1);
                if (old == 3) {
                    arrive[slot] = 0;
                    __threadfence_block();
                    *(volatile int*)&ready[slot] = s;
                }
            }
            #pragma unroll
            for (int k = 0; k < 8; k++) L[k] = N[k];
        }
    }

    __syncthreads();   // rejoin all 512

    const int fb = nsteps & 1;
    if (tid < 64) {
        if (dir == 0) g_fv[b][tid] = Abuf[fb][tid];
        else          g_bv[b][tid] = Abuf[fb][tid];
    }
    if (tid == 0) {
        const float off = (float)K * 0.6931471805599453f + (dir ? 0.f : m0);
        if (dir == 0) g_fo[b] = off; else g_bo[b] = off;
    }

    // ---- dir==0 epilogue: path score for batch b ----
    if (dir == 0) {
        const int ti = tid & 255;
        const unsigned wd = tu[ti];
        const unsigned h0 = wd & 0xFFFFu, h1 = wd >> 16;
        const float    f  = __uint_as_float(wd);
        int okA = (ti & 1) ? (wd == 0u) : (wd < 64u);
        int okB = (wd < 64u);
        int okI = (h0 < 64u) && (h1 < 64u);
        int okE = ((wd & 0xC0C0C0C0u) == 0u);
        int okC = (wd == 0u) || (f >= 1.f && f < 64.f && f == floorf(f));
        int okF = bf16_ok(h0) && bf16_ok(h1);
        okA = __syncthreads_and(okA);
        okB = __syncthreads_and(okB);
        okI = __syncthreads_and(okI);
        okE = __syncthreads_and(okE);
        okC = __syncthreads_and(okC);
        okF = __syncthreads_and(okF);
        const int mode = okA ? 0 : okB ? 1 : okI ? 2 : okE ? 3 : okC ? 4 : okF ? 5 : 6;

        float v = 0.f; int c = 0;
        if (tid < 256) {
            const int row = b * (SEQ + 1);
            const int i0 = decode_tgt(tu, mode, row + tid);
            const int i1 = decode_tgt(tu, mode, row + tid + 1);
            if (sM[tid]) {
                v = emits[(size_t)(tid * B_ + b) * TILE + i1 * 64 + i0];
                c = 1;
            }
        }
        #pragma unroll
        for (int o = 16; o; o >>= 1) {
            v += __shfl_xor_sync(~0u, v, o);
            c += __shfl_xor_sync(~0u, c, o);
        }
        if (lane == 0) { sv[wid] = v; scnt[wid] = c; }
        __syncthreads();
        if (tid == 0) {
            float tv = 0.f; int tc = 0;
            #pragma unroll
            for (int k = 0; k < 16; k++) { tv += sv[k]; tc += scnt[k]; }
            g_sc[b] = tv;
            g_ct[b] = tc;
        }
    }

    // ---- arrive; block 0 finishes the loss ----
    __threadfence();
    __syncthreads();
    if (tid == 0) atomicAdd(&g_done, 1);

    if (blk == 0) {
        if (tid == 0) {
            while (atomicAdd(&g_done, 0) < 64) __nanosleep(64);
            __threadfence();
        }
        __syncthreads();

        double accd = 0.0; int ctd = 0;
        for (int bb = wid; bb < 32; bb += 16) {
            float part = g_fv[bb][lane] * g_bv[bb][lane]
                       + g_fv[bb][lane + 32] * g_bv[bb][lane + 32];
            #pragma unroll
            for (int o = 16; o; o >>= 1) part += __shfl_xor_sync(~0u, part, o);
            if (lane == 0) {
                accd += (double)(logf(part) + g_fo[bb] + g_bo[bb]) - (double)g_sc[bb];
                ctd  += g_ct[bb];
            }
        }
        if (lane == 0) { sAcc[wid] = accd; sCt2[wid] = ctd; }
        __syncthreads();
        if (tid == 0) {
            double sd = 0.0; int cd = 0;
            #pragma unroll
            for (int k = 0; k < 16; k++) { sd += sAcc[k]; cd += sCt2[k]; }
            out[0] = (float)(sd / (double)cd);
            __threadfence();
            g_done = 0;   // reset for next graph replay
        }
    }
}

extern "C" void kernel_launch(void* const* d_in, const int* in_sizes, int n_in,
                              void* d_out, int out_size)
{
    int ie = 0;
    for (int k = 1; k < n_in; k++) if (in_sizes[k] > in_sizes[ie]) ie = k;
    int im = -1, it = -1;
    for (int k = 0; k < n_in; k++) {
        if (k == ie) continue;
        if (in_sizes[k] == 8192 && im < 0) im = k; else it = k;
    }
    if (im < 0) { im = 2; }
    if (it < 0) { it = (im == 1) ? 2 : 1; }

    const float*         emits = (const float*)d_in[ie];
    const unsigned*      tg    = (const unsigned*)d_in[it];
    const unsigned char* mask  = (const unsigned char*)d_in[im];

    const int smem_bytes = RSLOT * 2048 * 4;   // 65536
    cudaFuncSetAttribute(crf_fused, cudaFuncAttributeMaxDynamicSharedMemorySize, smem_bytes);

    crf_fused<<<64, 512, smem_bytes>>>(emits, mask, tg, (float*)d_out);
}